// round 4
// baseline (speedup 1.0000x reference)
#include <cuda_runtime.h>
#include <math.h>
#include <stdint.h>

#define S_TOK 8192
#define DM    1024
#define FFDIM 4096
#define NE    8
#define CAP   1280

#define BM 128
#define BN 128
#define BK 16
#define STAGES 4
#define RS 20                          // row stride (floats) for A and B stages
#define A_ST_BYTES (BM * RS * 4)       // 10240
#define B_ST_BYTES (BN * RS * 4)       // 10240
#define STG_BYTES  (A_ST_BYTES + B_ST_BYTES)
#define SMEM_BYTES (STAGES * STG_BYTES)   // 81920

// ---------------- scratch (device globals; no allocation allowed) ----------------
__device__ int   g_topk_i[S_TOK * 2];
__device__ float g_topk_w[S_TOK * 2];
__device__ int   g_slot[S_TOK * 2];
__device__ int   g_idx[NE * CAP];
__device__ int   g_cnt[NE];
__device__ float g_xin[(size_t)NE * CAP * DM];      // gathered + tf32-rounded x (zero padded)
__device__ float g_w1t[(size_t)NE * FFDIM * DM];    // w1 -> [e][FF][DM] K-major, rounded
__device__ float g_w2t[(size_t)NE * DM * FFDIM];    // w2 -> [e][DM][FF] K-major, rounded
__device__ float g_h  [(size_t)NE * CAP * FFDIM];   // hidden (rounded in epilogue)
__device__ float g_oute[(size_t)NE * CAP * DM];     // expert outputs

__device__ __forceinline__ float to_tf32(float x) {
    unsigned u;
    asm("cvt.rna.tf32.f32 %0, %1;" : "=r"(u) : "f"(x));
    return __uint_as_float(u);
}

__device__ __forceinline__ void mma_tf32(float* d, const unsigned* a, const unsigned* b) {
    asm volatile(
        "mma.sync.aligned.m16n8k8.row.col.f32.tf32.tf32.f32 "
        "{%0,%1,%2,%3}, {%4,%5,%6,%7}, {%8,%9}, {%0,%1,%2,%3};\n"
        : "+f"(d[0]), "+f"(d[1]), "+f"(d[2]), "+f"(d[3])
        : "r"(a[0]), "r"(a[1]), "r"(a[2]), "r"(a[3]), "r"(b[0]), "r"(b[1]));
}

__device__ __forceinline__ void cp16(unsigned dst, const void* src) {
    asm volatile("cp.async.ca.shared.global [%0], [%1], 16;\n" :: "r"(dst), "l"(src));
}
__device__ __forceinline__ void cp_commit() { asm volatile("cp.async.commit_group;\n"); }
__device__ __forceinline__ void cp_wait2()  { asm volatile("cp.async.wait_group 2;\n"); }

// ---------------- gating ----------------
__global__ __launch_bounds__(256) void gate_kernel(const float* __restrict__ x,
                                                   const float* __restrict__ gw,
                                                   const float* __restrict__ gb) {
    __shared__ float sgw[DM * 9];
    int tid = threadIdx.x;
    for (int i = tid; i < DM * NE; i += 256) sgw[(i >> 3) * 9 + (i & 7)] = gw[i];
    __syncthreads();

    int warp = tid >> 5, lane = tid & 31;
    int t = blockIdx.x * 8 + warp;
    const float* xr = x + (size_t)t * DM;
    float acc[NE];
#pragma unroll
    for (int e = 0; e < NE; e++) acc[e] = 0.f;
    for (int d = lane; d < DM; d += 32) {
        float xv = xr[d];
        const float* g = &sgw[d * 9];
#pragma unroll
        for (int e = 0; e < NE; e++) acc[e] += xv * g[e];
    }
#pragma unroll
    for (int e = 0; e < NE; e++) {
#pragma unroll
        for (int off = 16; off; off >>= 1)
            acc[e] += __shfl_xor_sync(0xffffffffu, acc[e], off);
    }
    if (lane == 0) {
        float l[NE];
#pragma unroll
        for (int e = 0; e < NE; e++) l[e] = acc[e] + gb[e];
        int i0 = 0;
#pragma unroll
        for (int e = 1; e < NE; e++) if (l[e] > l[i0]) i0 = e;
        int i1 = (i0 == 0) ? 1 : 0;
#pragma unroll
        for (int e = 0; e < NE; e++) if (e != i0 && l[e] > l[i1]) i1 = e;
        float p1 = expf(l[i1] - l[i0]);
        float w0 = 1.f / (1.f + p1);
        g_topk_i[2 * t] = i0; g_topk_i[2 * t + 1] = i1;
        g_topk_w[2 * t] = w0; g_topk_w[2 * t + 1] = 1.f - w0;
    }
}

// ---------------- routing ----------------
__global__ __launch_bounds__(256) void route_kernel() {
    __shared__ int wsum[8];
    __shared__ int run[NE];
    int tid = threadIdx.x, lane = tid & 31, warp = tid >> 5;
    if (tid < NE) run[tid] = 0;
    __syncthreads();

    for (int base = 0; base < S_TOK; base += 256) {
        int t = base + tid;
        int i0 = g_topk_i[2 * t], i1 = g_topk_i[2 * t + 1];
        int rank0 = 0, rank1 = 0;
        for (int e = 0; e < NE; e++) {
            int v = (i0 == e || i1 == e) ? 1 : 0;
#pragma unroll
            for (int off = 1; off < 32; off <<= 1) {
                int u = __shfl_up_sync(0xffffffffu, v, off);
                if (lane >= off) v += u;
            }
            if (lane == 31) wsum[warp] = v;
            __syncthreads();
            int woff = 0, total = 0;
#pragma unroll
            for (int w = 0; w < 8; w++) { int s = wsum[w]; total += s; if (w < warp) woff += s; }
            int rank = run[e] + woff + v;
            if (i0 == e) rank0 = rank;
            if (i1 == e) rank1 = rank;
            __syncthreads();
            if (tid == 0) run[e] += total;
        }
        int s0 = (rank0 <= CAP) ? rank0 - 1 : -1;
        int s1 = (rank1 <= CAP) ? rank1 - 1 : -1;
        g_slot[2 * t] = s0; g_slot[2 * t + 1] = s1;
        if (s0 >= 0) g_idx[i0 * CAP + s0] = t;
        if (s1 >= 0) g_idx[i1 * CAP + s1] = t;
    }
    __syncthreads();
    if (tid < NE) g_cnt[tid] = min(run[tid], CAP);
}

// ---------------- gather x -> g_xin (rounded, zero-padded) ----------------
__global__ __launch_bounds__(256) void xin_kernel(const float* __restrict__ x) {
    int c = blockIdx.x, e = blockIdx.y;
    int tok = (c < g_cnt[e]) ? g_idx[e * CAP + c] : -1;
    float* dst = g_xin + ((size_t)e * CAP + c) * DM + threadIdx.x * 4;
    if (tok < 0) {
        *reinterpret_cast<float4*>(dst) = make_float4(0.f, 0.f, 0.f, 0.f);
    } else {
        float4 v = *reinterpret_cast<const float4*>(x + (size_t)tok * DM + threadIdx.x * 4);
        v.x = to_tf32(v.x); v.y = to_tf32(v.y); v.z = to_tf32(v.z); v.w = to_tf32(v.w);
        *reinterpret_cast<float4*>(dst) = v;
    }
}

// ---------------- transpose + round weights: src[e][R][C] -> dst[e][C][R] ----------------
template<bool W1>
__global__ __launch_bounds__(256) void wtr_kernel(const float* __restrict__ src) {
    constexpr int R = W1 ? DM : FFDIM;
    constexpr int C = W1 ? FFDIM : DM;
    float* dst = W1 ? g_w1t : g_w2t;
    __shared__ float tile[32][33];
    int e = blockIdx.z;
    int c0 = blockIdx.x * 32, r0 = blockIdx.y * 32;
    const float* s = src + (size_t)e * R * C;
    float* d = dst + (size_t)e * R * C;
    int tx = threadIdx.x & 31, ty = threadIdx.x >> 5;   // 32x8
#pragma unroll
    for (int i = 0; i < 32; i += 8)
        tile[ty + i][tx] = s[(size_t)(r0 + ty + i) * C + c0 + tx];
    __syncthreads();
#pragma unroll
    for (int i = 0; i < 32; i += 8)
        d[(size_t)(c0 + ty + i) * R + r0 + tx] = to_tf32(tile[tx][ty + i]);
}

// ---------------- expert GEMM: tf32 mma.sync, pre-rounded K-major operands ----------------
// Slot permutation: logical mma k-slots (tig, tig+4) <- physical columns (2*tig, 2*tig+1),
// applied identically to A and B (sum over k is permutation-invariant).
// PHASE1: A=g_xin[e][CAP][DM], B=g_w1t[e][FF][DM], Out=g_h (relu(.+b1), rounded)
// else  : A=g_h [e][CAP][FF], B=g_w2t[e][DM][FF], Out=g_oute (.+b2)
template<bool PHASE1>
__global__ __launch_bounds__(256, 2)
void gemm_kernel(const float* __restrict__ biasGlob) {
    constexpr int KDIM = PHASE1 ? DM : FFDIM;
    constexpr int NDIM = PHASE1 ? FFDIM : DM;
    constexpr int NIT = KDIM / BK;

    extern __shared__ float smem[];

    const int e = blockIdx.z;
    const int rowBase = blockIdx.y * BM;
    const int nBase = blockIdx.x * BN;
    const int tid = threadIdx.x;

    const float* Ab = (PHASE1 ? g_xin : g_h) + ((size_t)e * CAP + rowBase) * KDIM;
    const float* Bb = (PHASE1 ? g_w1t : g_w2t) + ((size_t)e * NDIM + nBase) * KDIM;
    const float* bias = biasGlob + e * NDIM;
    float* Out = (PHASE1 ? g_h : g_oute) + (size_t)e * CAP * NDIM;

    const unsigned smem_base = (unsigned)__cvta_generic_to_shared(smem);

    const int ldRow0 = tid >> 2, ldC4 = (tid & 3);   // 64 rows x 4 chunks per pass

    auto load_stage = [&](int s, int kk) {
        unsigned aBase = smem_base + s * STG_BYTES;
        unsigned bBase = aBase + A_ST_BYTES;
#pragma unroll
        for (int i = 0; i < 2; i++) {
            int row = ldRow0 + i * 64;
            cp16(aBase + (row * RS + ldC4 * 4) * 4, Ab + (size_t)row * KDIM + kk + ldC4 * 4);
            cp16(bBase + (row * RS + ldC4 * 4) * 4, Bb + (size_t)row * KDIM + kk + ldC4 * 4);
        }
    };

    float acc[4][4][4];
#pragma unroll
    for (int mt = 0; mt < 4; mt++)
#pragma unroll
        for (int nt = 0; nt < 4; nt++)
#pragma unroll
            for (int i = 0; i < 4; i++) acc[mt][nt][i] = 0.f;

    const int warp = tid >> 5, lane = tid & 31;
    const int wm = warp >> 2, wn = warp & 3;       // 2x4 warp grid; warp tile 64x32
    const int gid = lane >> 2, tig = lane & 3;
    const int t2 = 2 * tig;

#pragma unroll
    for (int s = 0; s < STAGES - 1; s++) { load_stage(s, s * BK); cp_commit(); }

    for (int k = 0; k < NIT; k++) {
        cp_wait2();
        __syncthreads();

        int nk = k + STAGES - 1;
        if (nk < NIT) load_stage(nk & (STAGES - 1), nk * BK);
        cp_commit();

        const float* As = smem + (k & (STAGES - 1)) * (STG_BYTES / 4);
        const float* Bs = As + (A_ST_BYTES / 4);

#pragma unroll
        for (int kf = 0; kf < BK; kf += 8) {
            unsigned a[4][4], b[4][2];
#pragma unroll
            for (int mt = 0; mt < 4; mt++) {
                int r = wm * 64 + mt * 16 + gid;
                float2 lo = *reinterpret_cast<const float2*>(&As[r * RS + kf + t2]);
                float2 hi = *reinterpret_cast<const float2*>(&As[(r + 8) * RS + kf + t2]);
                a[mt][0] = __float_as_uint(lo.x);
                a[mt][1] = __float_as_uint(hi.x);
                a[mt][2] = __float_as_uint(lo.y);
                a[mt][3] = __float_as_uint(hi.y);
            }
#pragma unroll
            for (int nt = 0; nt < 4; nt++) {
                int c = wn * 32 + nt * 8 + gid;
                float2 bf = *reinterpret_cast<const float2*>(&Bs[c * RS + kf + t2]);
                b[nt][0] = __float_as_uint(bf.x);
                b[nt][1] = __float_as_uint(bf.y);
            }
#pragma unroll
            for (int mt = 0; mt < 4; mt++)
#pragma unroll
                for (int nt = 0; nt < 4; nt++)
                    mma_tf32(acc[mt][nt], a[mt], b[nt]);
        }
    }

    // epilogue: + bias (, relu + round), store
#pragma unroll
    for (int mt = 0; mt < 4; mt++) {
        int r0 = rowBase + wm * 64 + mt * 16 + gid;
#pragma unroll
        for (int nt = 0; nt < 4; nt++) {
            int c = nBase + wn * 32 + nt * 8 + 2 * tig;
            float bv0 = bias[c], bv1 = bias[c + 1];
            float v00 = acc[mt][nt][0] + bv0;
            float v01 = acc[mt][nt][1] + bv1;
            float v10 = acc[mt][nt][2] + bv0;
            float v11 = acc[mt][nt][3] + bv1;
            if (PHASE1) {
                v00 = to_tf32(fmaxf(v00, 0.f)); v01 = to_tf32(fmaxf(v01, 0.f));
                v10 = to_tf32(fmaxf(v10, 0.f)); v11 = to_tf32(fmaxf(v11, 0.f));
            }
            *reinterpret_cast<float2*>(Out + (size_t)r0 * NDIM + c) = make_float2(v00, v01);
            *reinterpret_cast<float2*>(Out + (size_t)(r0 + 8) * NDIM + c) = make_float2(v10, v11);
        }
    }
}

// ---------------- combine ----------------
__global__ __launch_bounds__(256) void combine_kernel(float* __restrict__ out) {
    int t = blockIdx.x;
    int i0 = g_topk_i[2 * t], i1 = g_topk_i[2 * t + 1];
    int s0 = g_slot[2 * t], s1 = g_slot[2 * t + 1];
    float w0 = g_topk_w[2 * t], w1v = g_topk_w[2 * t + 1];
    int d = threadIdx.x * 4;
    float4 a = make_float4(0.f, 0.f, 0.f, 0.f);
    if (s0 >= 0) {
        float4 v = *reinterpret_cast<const float4*>(g_oute + ((size_t)i0 * CAP + s0) * DM + d);
        a.x += w0 * v.x; a.y += w0 * v.y; a.z += w0 * v.z; a.w += w0 * v.w;
    }
    if (s1 >= 0) {
        float4 v = *reinterpret_cast<const float4*>(g_oute + ((size_t)i1 * CAP + s1) * DM + d);
        a.x += w1v * v.x; a.y += w1v * v.y; a.z += w1v * v.z; a.w += w1v * v.w;
    }
    *reinterpret_cast<float4*>(out + (size_t)t * DM + d) = a;
}

// ---------------- launch ----------------
extern "C" void kernel_launch(void* const* d_in, const int* in_sizes, int n_in,
                              void* d_out, int out_size) {
    (void)in_sizes; (void)n_in; (void)out_size;
    const float* x      = (const float*)d_in[0];
    const float* gate_w = (const float*)d_in[1];
    const float* gate_b = (const float*)d_in[2];
    const float* w1     = (const float*)d_in[3];
    const float* b1     = (const float*)d_in[4];
    const float* w2     = (const float*)d_in[5];
    const float* b2     = (const float*)d_in[6];
    float* out = (float*)d_out;

    static bool attr_done = false;
    if (!attr_done) {
        cudaFuncSetAttribute(gemm_kernel<true>,
                             cudaFuncAttributeMaxDynamicSharedMemorySize, SMEM_BYTES);
        cudaFuncSetAttribute(gemm_kernel<false>,
                             cudaFuncAttributeMaxDynamicSharedMemorySize, SMEM_BYTES);
        attr_done = true;
    }

    gate_kernel<<<S_TOK / 8, 256>>>(x, gate_w, gate_b);
    route_kernel<<<1, 256>>>();
    xin_kernel<<<dim3(CAP, NE), 256>>>(x);
    wtr_kernel<true ><<<dim3(FFDIM / 32, DM / 32, NE), 256>>>(w1);
    wtr_kernel<false><<<dim3(DM / 32, FFDIM / 32, NE), 256>>>(w2);
    gemm_kernel<true >
        <<<dim3(FFDIM / BN, CAP / BM, NE), 256, SMEM_BYTES>>>(b1);
    gemm_kernel<false>
        <<<dim3(DM / BN,    CAP / BM, NE), 256, SMEM_BYTES>>>(b2);
    combine_kernel<<<S_TOK, 256>>>(out);
}